// round 2
// baseline (speedup 1.0000x reference)
#include <cuda_runtime.h>
#include <cuda_fp16.h>
#include <cuda_bf16.h>
#include <cstdint>

#define BSZ 8192
#define DIM 256

// ---------------- device globals (scratch; no runtime allocation) ----------------
__device__ __half         g_K[(size_t)BSZ * BSZ];          // 134 MB: K = exp(G-1) in fp16
__device__ __nv_bfloat16  g_imgb[BSZ * DIM];
__device__ __nv_bfloat16  g_txtb[BSZ * DIM];
__device__ float g_vimg[BSZ], g_vtxt[BSZ], g_uimg[BSZ], g_utxt[BSZ];
__device__ float g_rA[BSZ], g_cA[BSZ], g_rB[BSZ], g_cB[BSZ];
__device__ float g_Srow[BSZ];   // img-direction row exp-sums
__device__ float g_part[BSZ];   // per-row loss terms

// ---------------- fp32 -> bf16 convert ----------------
__global__ void cvt_kernel(const float* __restrict__ img, const float* __restrict__ txt) {
    int i = blockIdx.x * blockDim.x + threadIdx.x;
    if (i < BSZ * DIM) {
        g_imgb[i] = __float2bfloat16_rn(img[i]);
        g_txtb[i] = __float2bfloat16_rn(txt[i]);
    }
}

// ---------------- GEMM: K = exp(img @ txt^T - 1), bf16 mma.sync, fp16 out ----------------
// Tile: BM=128, BN=64, full K-dim=256 resident in smem. 8 warps: 4(m) x 2(n), warp tile 32x32.
#define SP 264   // padded smem row stride (halfs): (132 words) % 32 = 4 -> conflict-free frags
#define GEMM_SMEM_BYTES ((128 * SP + 64 * SP) * 2)

__device__ __forceinline__ void mma_bf16(float c[4], const uint32_t a[4], const uint32_t b[2]) {
    asm volatile(
        "mma.sync.aligned.m16n8k16.row.col.f32.bf16.bf16.f32 "
        "{%0,%1,%2,%3}, {%4,%5,%6,%7}, {%8,%9}, {%0,%1,%2,%3};\n"
        : "+f"(c[0]), "+f"(c[1]), "+f"(c[2]), "+f"(c[3])
        : "r"(a[0]), "r"(a[1]), "r"(a[2]), "r"(a[3]), "r"(b[0]), "r"(b[1]));
}

__global__ __launch_bounds__(256) void gemm_exp_kernel() {
    extern __shared__ char smraw[];
    __nv_bfloat16* As = reinterpret_cast<__nv_bfloat16*>(smraw);
    __nv_bfloat16* Bs = As + 128 * SP;

    const int tid  = threadIdx.x;
    const int lane = tid & 31, warp = tid >> 5;
    const int g = lane >> 2, tq = lane & 3;
    const int wm = warp & 3, wn = warp >> 2;

    const int nTile = blockIdx.x * 64;    // over txt rows (columns of G)
    const int mTile = blockIdx.y * 128;   // over img rows

    // load A tile (128 x 256 bf16) as 16B vectors
    #pragma unroll
    for (int it = 0; it < 2; it++) {
        int idx = tid + it * 256;              // 512 of 4096 vecs... need 16 per thread
        (void)idx;
    }
    for (int idx = tid; idx < 128 * 32; idx += 256) {
        int r = idx >> 5, c8 = idx & 31;
        const float4* src = reinterpret_cast<const float4*>(g_imgb + (size_t)(mTile + r) * DIM + c8 * 8);
        *reinterpret_cast<float4*>(As + r * SP + c8 * 8) = *src;
    }
    // load B tile (64 x 256 bf16)
    for (int idx = tid; idx < 64 * 32; idx += 256) {
        int r = idx >> 5, c8 = idx & 31;
        const float4* src = reinterpret_cast<const float4*>(g_txtb + (size_t)(nTile + r) * DIM + c8 * 8);
        *reinterpret_cast<float4*>(Bs + r * SP + c8 * 8) = *src;
    }
    __syncthreads();

    float c[2][4][4] = {};
    #pragma unroll
    for (int ks = 0; ks < 16; ks++) {
        const int k0 = ks * 16;
        uint32_t a[2][4], b[4][2];
        #pragma unroll
        for (int mi = 0; mi < 2; mi++) {
            int rb = wm * 32 + mi * 16;
            a[mi][0] = *reinterpret_cast<const uint32_t*>(As + (rb + g)     * SP + k0 + 2 * tq);
            a[mi][1] = *reinterpret_cast<const uint32_t*>(As + (rb + g + 8) * SP + k0 + 2 * tq);
            a[mi][2] = *reinterpret_cast<const uint32_t*>(As + (rb + g)     * SP + k0 + 2 * tq + 8);
            a[mi][3] = *reinterpret_cast<const uint32_t*>(As + (rb + g + 8) * SP + k0 + 2 * tq + 8);
        }
        #pragma unroll
        for (int ni = 0; ni < 4; ni++) {
            int nb = wn * 32 + ni * 8;
            b[ni][0] = *reinterpret_cast<const uint32_t*>(Bs + (nb + g) * SP + k0 + 2 * tq);
            b[ni][1] = *reinterpret_cast<const uint32_t*>(Bs + (nb + g) * SP + k0 + 2 * tq + 8);
        }
        #pragma unroll
        for (int mi = 0; mi < 2; mi++)
            #pragma unroll
            for (int ni = 0; ni < 4; ni++)
                mma_bf16(c[mi][ni], a[mi], b[ni]);
    }

    // epilogue: K = half(exp(G - 1))
    #pragma unroll
    for (int mi = 0; mi < 2; mi++) {
        #pragma unroll
        for (int ni = 0; ni < 4; ni++) {
            int row0 = mTile + wm * 32 + mi * 16 + g;
            int col  = nTile + wn * 32 + ni * 8 + 2 * tq;
            __half2 h01 = __floats2half2_rn(__expf(c[mi][ni][0] - 1.0f), __expf(c[mi][ni][1] - 1.0f));
            __half2 h23 = __floats2half2_rn(__expf(c[mi][ni][2] - 1.0f), __expf(c[mi][ni][3] - 1.0f));
            *reinterpret_cast<__half2*>(g_K + (size_t)row0 * BSZ + col)       = h01;
            *reinterpret_cast<__half2*>(g_K + (size_t)(row0 + 8) * BSZ + col) = h23;
        }
    }
}

// ---------------- init ----------------
__global__ void init_kernel() {
    int i = blockIdx.x * blockDim.x + threadIdx.x;
    if (i < BSZ) { g_vimg[i] = 1.0f; g_vtxt[i] = 1.0f; g_cA[i] = 0.0f; g_cB[i] = 0.0f; }
}

// ---------------- dual matvec pass: y1 = K x1 (rows, direct), y2 = K^T x2 (cols, atomic) ----
// mode 0: x1=v_img, x2=v_txt, y1=rA, y2=cA      (row-steps of both chains)
// mode 1: x1=u_txt, x2=u_img, y1=rB, y2=cB      (col-steps of both chains)
#define RPB 32
__global__ __launch_bounds__(256, 2) void pass_dual(int mode) {
    const float *x1, *x2; float *y1, *y2;
    if (mode == 0) { x1 = g_vimg; x2 = g_vtxt; y1 = g_rA; y2 = g_cA; }
    else           { x1 = g_utxt; x2 = g_uimg; y1 = g_rB; y2 = g_cB; }

    const int t = threadIdx.x, lane = t & 31, warp = t >> 5;
    float v[4][8], cp[4][8];
    #pragma unroll
    for (int gg = 0; gg < 4; gg++)
        #pragma unroll
        for (int k = 0; k < 8; k++) {
            v[gg][k]  = x1[(gg * 256 + t) * 8 + k];
            cp[gg][k] = 0.0f;
        }

    __shared__ float srow[RPB][8];
    const int r0 = blockIdx.x * RPB;

    for (int r = 0; r < RPB; r++) {
        const __half* Kr = g_K + (size_t)(r0 + r) * BSZ;
        const float x2r = x2[r0 + r];
        float acc = 0.0f;
        #pragma unroll
        for (int gg = 0; gg < 4; gg++) {
            uint4 q = *reinterpret_cast<const uint4*>(Kr + (gg * 256 + t) * 8);
            const __half2* hp = reinterpret_cast<const __half2*>(&q);
            #pragma unroll
            for (int j = 0; j < 4; j++) {
                float2 f = __half22float2(hp[j]);
                acc = fmaf(f.x, v[gg][2 * j],     acc);
                acc = fmaf(f.y, v[gg][2 * j + 1], acc);
                cp[gg][2 * j]     = fmaf(f.x, x2r, cp[gg][2 * j]);
                cp[gg][2 * j + 1] = fmaf(f.y, x2r, cp[gg][2 * j + 1]);
            }
        }
        #pragma unroll
        for (int off = 16; off > 0; off >>= 1) acc += __shfl_xor_sync(0xffffffffu, acc, off);
        if (lane == 0) srow[r][warp] = acc;
    }
    __syncthreads();
    if (t < RPB) {
        float s = 0.0f;
        #pragma unroll
        for (int w = 0; w < 8; w++) s += srow[t][w];
        y1[r0 + t] = s;
    }
    #pragma unroll
    for (int gg = 0; gg < 4; gg++)
        #pragma unroll
        for (int k = 0; k < 8; k++)
            atomicAdd(&y2[(gg * 256 + t) * 8 + k], cp[gg][k]);
}

// ---------------- final pass: softmax denominators ----------------
// Srow[i] = sum_j exp(u_img[i] K[i,j] v_img[j])   (direct)
// cA[c]   = sum_r exp(u_txt[c] K[r,c] v_txt[r])   (atomic; cA pre-zeroed)
__global__ __launch_bounds__(256, 2) void pass_final() {
    const int t = threadIdx.x, lane = t & 31, warp = t >> 5;
    float vi[4][8], ut[4][8], cp[4][8];
    #pragma unroll
    for (int gg = 0; gg < 4; gg++)
        #pragma unroll
        for (int k = 0; k < 8; k++) {
            int c = (gg * 256 + t) * 8 + k;
            vi[gg][k] = g_vimg[c];
            ut[gg][k] = g_utxt[c];
            cp[gg][k] = 0.0f;
        }

    __shared__ float srow[RPB][8];
    const int r0 = blockIdx.x * RPB;

    for (int r = 0; r < RPB; r++) {
        const __half* Kr = g_K + (size_t)(r0 + r) * BSZ;
        const float ur  = g_uimg[r0 + r];
        const float vtr = g_vtxt[r0 + r];
        float acc = 0.0f;
        #pragma unroll
        for (int gg = 0; gg < 4; gg++) {
            uint4 q = *reinterpret_cast<const uint4*>(Kr + (gg * 256 + t) * 8);
            const __half2* hp = reinterpret_cast<const __half2*>(&q);
            #pragma unroll
            for (int j = 0; j < 4; j++) {
                float2 f = __half22float2(hp[j]);
                acc += __expf(ur * f.x * vi[gg][2 * j]);
                acc += __expf(ur * f.y * vi[gg][2 * j + 1]);
                cp[gg][2 * j]     += __expf(ut[gg][2 * j]     * f.x * vtr);
                cp[gg][2 * j + 1] += __expf(ut[gg][2 * j + 1] * f.y * vtr);
            }
        }
        #pragma unroll
        for (int off = 16; off > 0; off >>= 1) acc += __shfl_xor_sync(0xffffffffu, acc, off);
        if (lane == 0) srow[r][warp] = acc;
    }
    __syncthreads();
    if (t < RPB) {
        float s = 0.0f;
        #pragma unroll
        for (int w = 0; w < 8; w++) s += srow[t][w];
        g_Srow[r0 + t] = s;
    }
    #pragma unroll
    for (int gg = 0; gg < 4; gg++)
        #pragma unroll
        for (int k = 0; k < 8; k++)
            atomicAdd(&g_cA[(gg * 256 + t) * 8 + k], cp[gg][k]);
}

// ---------------- scalar update kernels ----------------
__global__ void upd_u_kernel() {
    int i = blockIdx.x * blockDim.x + threadIdx.x;
    if (i < BSZ) {
        g_uimg[i] = 1.0f / g_rA[i];
        g_utxt[i] = 1.0f / g_cA[i];
        g_cB[i] = 0.0f;                 // prep atomic target for pass B
    }
}

__global__ void upd_v_kernel() {
    int i = blockIdx.x * blockDim.x + threadIdx.x;
    if (i < BSZ) {
        // img chain: colsum = v_img * (K^T u_img) = v_img * cB
        float tt = g_vimg[i] * g_cB[i];
        float f1 = fmaxf(0.5f / tt, 1.0f);
        tt *= f1;
        float f2 = fminf(4.5f / tt, 1.0f);
        g_vimg[i] *= f1 * f2;
        // txt chain: colsum' = v_txt * (K u_txt) = v_txt * rB
        float tu = g_vtxt[i] * g_rB[i];
        float h1 = fmaxf(0.5f / tu, 1.0f);
        tu *= h1;
        float h2 = fminf(4.5f / tu, 1.0f);
        g_vtxt[i] *= h1 * h2;
        g_cA[i] = 0.0f;                 // prep atomic target for next pass A / final pass
    }
}

// ---------------- finalize ----------------
__global__ void finalize1_kernel(const int* __restrict__ labels) {
    int i = blockIdx.x * blockDim.x + threadIdx.x;
    if (i < BSZ) {
        int l = labels[i];
        float p1 = g_uimg[i] * __half2float(g_K[(size_t)i * BSZ + l]) * g_vimg[l];
        float p2 = g_utxt[i] * __half2float(g_K[(size_t)l * BSZ + i]) * g_vtxt[l];
        g_part[i] = (__logf(g_Srow[i]) - p1) + (__logf(g_cA[i]) - p2);
    }
}

__global__ void finalize2_kernel(float* __restrict__ out) {
    __shared__ float sm[1024];
    int t = threadIdx.x;
    float s = 0.0f;
    for (int i = t; i < BSZ; i += 1024) s += g_part[i];
    sm[t] = s;
    __syncthreads();
    for (int off = 512; off > 0; off >>= 1) {
        if (t < off) sm[t] += sm[t + off];
        __syncthreads();
    }
    if (t == 0) out[0] = sm[0] * (0.5f / (float)BSZ);
}

// ---------------- launch ----------------
extern "C" void kernel_launch(void* const* d_in, const int* in_sizes, int n_in,
                              void* d_out, int out_size) {
    const float* img    = (const float*)d_in[0];
    const float* txt    = (const float*)d_in[1];
    const int*   labels = (const int*)d_in[2];
    float* out = (float*)d_out;
    (void)in_sizes; (void)n_in; (void)out_size;

    cudaFuncSetAttribute(gemm_exp_kernel, cudaFuncAttributeMaxDynamicSharedMemorySize,
                         GEMM_SMEM_BYTES);

    cvt_kernel<<<(BSZ * DIM + 255) / 256, 256>>>(img, txt);

    dim3 ggrid(BSZ / 64, BSZ / 128);
    gemm_exp_kernel<<<ggrid, 256, GEMM_SMEM_BYTES>>>();

    init_kernel<<<BSZ / 256, 256>>>();

    for (int it = 0; it < 5; it++) {
        pass_dual<<<BSZ / RPB, 256>>>(0);   // rA = K v_img ; cA = K^T v_txt
        upd_u_kernel<<<BSZ / 256, 256>>>(); // u = 1/rowsums ; zero cB
        pass_dual<<<BSZ / RPB, 256>>>(1);   // rB = K u_txt ; cB = K^T u_img
        upd_v_kernel<<<BSZ / 256, 256>>>(); // v clamp updates ; zero cA
    }

    pass_final<<<BSZ / RPB, 256>>>();       // Srow (img), cA (txt) exp-sums
    finalize1_kernel<<<BSZ / 256, 256>>>(labels);
    finalize2_kernel<<<1, 1024>>>(out);
}

// round 3
// speedup vs baseline: 1.6557x; 1.6557x over previous
#include <cuda_runtime.h>
#include <cuda_fp16.h>
#include <cuda_bf16.h>
#include <cstdint>

#define BSZ 8192
#define DIM 256

// ---------------- device globals (scratch; no runtime allocation) ----------------
__device__ __half         g_K[(size_t)BSZ * BSZ];          // 134 MB: K = exp(G-1) in fp16
__device__ __nv_bfloat16  g_imgb[BSZ * DIM];
__device__ __nv_bfloat16  g_txtb[BSZ * DIM];
__device__ float g_vimg[BSZ], g_vtxt[BSZ], g_uimg[BSZ], g_utxt[BSZ];
__device__ float g_rA[BSZ], g_cA[BSZ], g_rB[BSZ], g_cB[BSZ];
__device__ float g_part[BSZ];

// ---------------- fp32 -> bf16 convert ----------------
__global__ void cvt_kernel(const float* __restrict__ img, const float* __restrict__ txt) {
    int i = blockIdx.x * blockDim.x + threadIdx.x;
    if (i < BSZ * DIM) {
        g_imgb[i] = __float2bfloat16_rn(img[i]);
        g_txtb[i] = __float2bfloat16_rn(txt[i]);
    }
}

// ================= GEMM: K = exp(img @ txt^T - 1) =================
// A tile 128x256 resident in smem; B tiles (64x256) double-buffered with cp.async
// across a strip of 1024 columns (16 tiles). Grid: (8 strips, 64 row tiles).
#define SP 264   // padded smem row stride (halfs) -> conflict-free fragment loads
#define NB 64
#define STRIPC 1024
#define NTILES (STRIPC / NB)   // 16
#define GEMM_SMEM_BYTES ((128 * SP + 2 * NB * SP) * 2)

__device__ __forceinline__ void mma_bf16(float c[4], const uint32_t a[4], const uint32_t b[2]) {
    asm volatile(
        "mma.sync.aligned.m16n8k16.row.col.f32.bf16.bf16.f32 "
        "{%0,%1,%2,%3}, {%4,%5,%6,%7}, {%8,%9}, {%0,%1,%2,%3};\n"
        : "+f"(c[0]), "+f"(c[1]), "+f"(c[2]), "+f"(c[3])
        : "r"(a[0]), "r"(a[1]), "r"(a[2]), "r"(a[3]), "r"(b[0]), "r"(b[1]));
}

__device__ __forceinline__ void cp_async16(void* smem_dst, const void* gsrc) {
    uint32_t sa = (uint32_t)__cvta_generic_to_shared(smem_dst);
    asm volatile("cp.async.cg.shared.global [%0], [%1], 16;\n" :: "r"(sa), "l"(gsrc));
}

__global__ __launch_bounds__(256, 1) void gemm_exp_kernel() {
    extern __shared__ __nv_bfloat16 sm[];
    __nv_bfloat16* As = sm;
    __nv_bfloat16* Bs = sm + 128 * SP;

    const int tid  = threadIdx.x;
    const int lane = tid & 31, warp = tid >> 5;
    const int g = lane >> 2, tq = lane & 3;
    const int wm = warp & 3, wn = warp >> 2;

    const int mTile  = blockIdx.y * 128;
    const int strip0 = blockIdx.x * STRIPC;

    // A tile: plain vector loads (once)
    for (int idx = tid; idx < 128 * 32; idx += 256) {
        int r = idx >> 5, c8 = idx & 31;
        *reinterpret_cast<float4*>(As + r * SP + c8 * 8) =
            *reinterpret_cast<const float4*>(g_imgb + (size_t)(mTile + r) * DIM + c8 * 8);
    }

    // prefetch B tile 0
    {
        __nv_bfloat16* Bd = Bs;
        for (int idx = tid; idx < NB * 32; idx += 256) {
            int r = idx >> 5, c8 = idx & 31;
            cp_async16(Bd + r * SP + c8 * 8,
                       g_txtb + (size_t)(strip0 + r) * DIM + c8 * 8);
        }
        asm volatile("cp.async.commit_group;\n");
    }

    for (int bt = 0; bt < NTILES; bt++) {
        if (bt + 1 < NTILES) {
            __nv_bfloat16* Bd = Bs + ((bt + 1) & 1) * NB * SP;
            const int nb0 = strip0 + (bt + 1) * NB;
            for (int idx = tid; idx < NB * 32; idx += 256) {
                int r = idx >> 5, c8 = idx & 31;
                cp_async16(Bd + r * SP + c8 * 8,
                           g_txtb + (size_t)(nb0 + r) * DIM + c8 * 8);
            }
            asm volatile("cp.async.commit_group;\n");
            asm volatile("cp.async.wait_group 1;\n");
        } else {
            asm volatile("cp.async.wait_group 0;\n");
        }
        __syncthreads();

        const __nv_bfloat16* Bb = Bs + (bt & 1) * NB * SP;
        float c[2][4][4];
        #pragma unroll
        for (int mi = 0; mi < 2; mi++)
            #pragma unroll
            for (int ni = 0; ni < 4; ni++)
                #pragma unroll
                for (int k = 0; k < 4; k++) c[mi][ni][k] = 0.0f;

        #pragma unroll
        for (int ks = 0; ks < 16; ks++) {
            const int k0 = ks * 16;
            uint32_t a[2][4], b[4][2];
            #pragma unroll
            for (int mi = 0; mi < 2; mi++) {
                int rb = wm * 32 + mi * 16;
                a[mi][0] = *reinterpret_cast<const uint32_t*>(As + (rb + g)     * SP + k0 + 2 * tq);
                a[mi][1] = *reinterpret_cast<const uint32_t*>(As + (rb + g + 8) * SP + k0 + 2 * tq);
                a[mi][2] = *reinterpret_cast<const uint32_t*>(As + (rb + g)     * SP + k0 + 2 * tq + 8);
                a[mi][3] = *reinterpret_cast<const uint32_t*>(As + (rb + g + 8) * SP + k0 + 2 * tq + 8);
            }
            #pragma unroll
            for (int ni = 0; ni < 4; ni++) {
                int nb = wn * 32 + ni * 8;
                b[ni][0] = *reinterpret_cast<const uint32_t*>(Bb + (nb + g) * SP + k0 + 2 * tq);
                b[ni][1] = *reinterpret_cast<const uint32_t*>(Bb + (nb + g) * SP + k0 + 2 * tq + 8);
            }
            #pragma unroll
            for (int mi = 0; mi < 2; mi++)
                #pragma unroll
                for (int ni = 0; ni < 4; ni++)
                    mma_bf16(c[mi][ni], a[mi], b[ni]);
        }

        // epilogue: K = half(exp(G - 1))
        const int nTile = strip0 + bt * NB;
        #pragma unroll
        for (int mi = 0; mi < 2; mi++) {
            #pragma unroll
            for (int ni = 0; ni < 4; ni++) {
                int row0 = mTile + wm * 32 + mi * 16 + g;
                int col  = nTile + wn * 32 + ni * 8 + 2 * tq;
                __half2 h01 = __floats2half2_rn(__expf(c[mi][ni][0] - 1.0f), __expf(c[mi][ni][1] - 1.0f));
                __half2 h23 = __floats2half2_rn(__expf(c[mi][ni][2] - 1.0f), __expf(c[mi][ni][3] - 1.0f));
                *reinterpret_cast<__half2*>(g_K + (size_t)row0 * BSZ + col)       = h01;
                *reinterpret_cast<__half2*>(g_K + (size_t)(row0 + 8) * BSZ + col) = h23;
            }
        }
        __syncthreads();
    }
}

// ---------------- init ----------------
__global__ void init_kernel() {
    int i = blockIdx.x * blockDim.x + threadIdx.x;
    if (i < BSZ) { g_vimg[i] = 1.0f; g_vtxt[i] = 1.0f; g_rA[i] = 0.0f; g_cA[i] = 0.0f; }
}

// ============== dual matvec pass: y1 += K x1 (rows), y2 += K^T x2 (cols) ==============
// mode 0: x1=v_img, x2=v_txt, y1=rA, y2=cA
// mode 1: x1=u_txt, x2=u_img, y1=rB, y2=cB
// Tile: PR rows x 2048 cols per block; thread owns 8 cols; 8 rows unrolled (MLP=8).
#define PR 64

// fold-reduce 8 per-thread row partials across a warp in 9 shuffles;
// result: every lane holds the full sum for row (lane & 7).
__device__ __forceinline__ float reduce8rows(const float a[8], int lane) {
    float b0, b1, b2, b3;
    {
        bool o = lane & 1;
        float lo, hi, s, r;
        lo = a[0]; hi = a[1]; s = o ? lo : hi; r = __shfl_xor_sync(0xffffffffu, s, 1); b0 = (o ? hi : lo) + r;
        lo = a[2]; hi = a[3]; s = o ? lo : hi; r = __shfl_xor_sync(0xffffffffu, s, 1); b1 = (o ? hi : lo) + r;
        lo = a[4]; hi = a[5]; s = o ? lo : hi; r = __shfl_xor_sync(0xffffffffu, s, 1); b2 = (o ? hi : lo) + r;
        lo = a[6]; hi = a[7]; s = o ? lo : hi; r = __shfl_xor_sync(0xffffffffu, s, 1); b3 = (o ? hi : lo) + r;
    }
    float c0, c1;
    {
        bool o = lane & 2;
        float lo, hi, s, r;
        lo = b0; hi = b1; s = o ? lo : hi; r = __shfl_xor_sync(0xffffffffu, s, 2); c0 = (o ? hi : lo) + r;
        lo = b2; hi = b3; s = o ? lo : hi; r = __shfl_xor_sync(0xffffffffu, s, 2); c1 = (o ? hi : lo) + r;
    }
    float d;
    {
        bool o = lane & 4;
        float s = o ? c0 : c1;
        float r = __shfl_xor_sync(0xffffffffu, s, 4);
        d = (o ? c1 : c0) + r;
    }
    d += __shfl_xor_sync(0xffffffffu, d, 8);
    d += __shfl_xor_sync(0xffffffffu, d, 16);
    return d;
}

__global__ __launch_bounds__(256) void pass_dual(int mode) {
    const float *x1, *x2; float *y1, *y2;
    if (mode == 0) { x1 = g_vimg; x2 = g_vtxt; y1 = g_rA; y2 = g_cA; }
    else           { x1 = g_utxt; x2 = g_uimg; y1 = g_rB; y2 = g_cB; }

    const int t = threadIdx.x, lane = t & 31;
    const int c  = blockIdx.x * 2048 + t * 8;
    const int r0 = blockIdx.y * PR;

    float v[8];
    #pragma unroll
    for (int k = 0; k < 8; k++) v[k] = x1[c + k];
    float cp[8];
    #pragma unroll
    for (int k = 0; k < 8; k++) cp[k] = 0.0f;

    __shared__ float srow[PR];
    __shared__ float sx2[PR];
    if (t < PR) { srow[t] = 0.0f; sx2[t] = x2[r0 + t]; }
    __syncthreads();

    for (int rb = 0; rb < PR; rb += 8) {
        uint4 q[8];
        #pragma unroll
        for (int rr = 0; rr < 8; rr++)
            q[rr] = *reinterpret_cast<const uint4*>(g_K + (size_t)(r0 + rb + rr) * BSZ + c);

        float acc[8];
        #pragma unroll
        for (int rr = 0; rr < 8; rr++) {
            const float x2r = sx2[rb + rr];
            const __half2* hp = reinterpret_cast<const __half2*>(&q[rr]);
            float a = 0.0f;
            #pragma unroll
            for (int j = 0; j < 4; j++) {
                float2 f = __half22float2(hp[j]);
                a = fmaf(f.x, v[2 * j],     a);
                a = fmaf(f.y, v[2 * j + 1], a);
                cp[2 * j]     = fmaf(f.x, x2r, cp[2 * j]);
                cp[2 * j + 1] = fmaf(f.y, x2r, cp[2 * j + 1]);
            }
            acc[rr] = a;
        }
        float d = reduce8rows(acc, lane);
        if (lane < 8) atomicAdd(&srow[rb + lane], d);
    }
    __syncthreads();
    if (t < PR) atomicAdd(&y1[r0 + t], srow[t]);
    #pragma unroll
    for (int k = 0; k < 8; k++) atomicAdd(&y2[c + k], cp[k]);
}

// ---------------- scalar update kernels ----------------
__global__ void upd_u_kernel() {
    int i = blockIdx.x * blockDim.x + threadIdx.x;
    if (i < BSZ) {
        g_uimg[i] = 1.0f / g_rA[i];
        g_utxt[i] = 1.0f / g_cA[i];
        g_rB[i] = 0.0f; g_cB[i] = 0.0f;
    }
}

__global__ void upd_v_kernel() {
    int i = blockIdx.x * blockDim.x + threadIdx.x;
    if (i < BSZ) {
        float tt = g_vimg[i] * g_cB[i];
        float f1 = fmaxf(0.5f / tt, 1.0f);
        tt *= f1;
        float f2 = fminf(4.5f / tt, 1.0f);
        g_vimg[i] *= f1 * f2;

        float tu = g_vtxt[i] * g_rB[i];
        float h1 = fmaxf(0.5f / tu, 1.0f);
        tu *= h1;
        float h2 = fminf(4.5f / tu, 1.0f);
        g_vtxt[i] *= h1 * h2;

        g_rA[i] = 0.0f; g_cA[i] = 0.0f;   // prep next pass-A / final pass
    }
}

// ---------------- finalize ----------------
// After final pass A: rA = K v_img, cA = K^T v_txt.
// Srow_i = sum_j exp(P_ij) ~= BSZ + u_i * rA_i   (P entries ~1e-4; quadratic term < 1e-3 abs)
__global__ void finalize1_kernel(const int* __restrict__ labels) {
    int i = blockIdx.x * blockDim.x + threadIdx.x;
    if (i < BSZ) {
        int l = labels[i];
        float p1 = g_uimg[i] * __half2float(g_K[(size_t)i * BSZ + l]) * g_vimg[l];
        float p2 = g_utxt[i] * __half2float(g_K[(size_t)l * BSZ + i]) * g_vtxt[l];
        float S1 = (float)BSZ + g_uimg[i] * g_rA[i];
        float S2 = (float)BSZ + g_utxt[i] * g_cA[i];
        g_part[i] = (__logf(S1) - p1) + (__logf(S2) - p2);
    }
}

__global__ void finalize2_kernel(float* __restrict__ out) {
    __shared__ float smr[1024];
    int t = threadIdx.x;
    float s = 0.0f;
    for (int i = t; i < BSZ; i += 1024) s += g_part[i];
    smr[t] = s;
    __syncthreads();
    for (int off = 512; off > 0; off >>= 1) {
        if (t < off) smr[t] += smr[t + off];
        __syncthreads();
    }
    if (t == 0) out[0] = smr[0] * (0.5f / (float)BSZ);
}

// ---------------- launch ----------------
extern "C" void kernel_launch(void* const* d_in, const int* in_sizes, int n_in,
                              void* d_out, int out_size) {
    const float* img    = (const float*)d_in[0];
    const float* txt    = (const float*)d_in[1];
    const int*   labels = (const int*)d_in[2];
    float* out = (float*)d_out;
    (void)in_sizes; (void)n_in; (void)out_size;

    cudaFuncSetAttribute(gemm_exp_kernel, cudaFuncAttributeMaxDynamicSharedMemorySize,
                         GEMM_SMEM_BYTES);

    cvt_kernel<<<(BSZ * DIM + 255) / 256, 256>>>(img, txt);

    dim3 ggrid(BSZ / STRIPC, BSZ / 128);   // (8, 64)
    gemm_exp_kernel<<<ggrid, 256, GEMM_SMEM_BYTES>>>();

    init_kernel<<<BSZ / 256, 256>>>();

    dim3 pgrid(4, BSZ / PR);               // (4, 128)
    for (int it = 0; it < 5; it++) {
        pass_dual<<<pgrid, 256>>>(0);      // rA += K v_img ; cA += K^T v_txt
        upd_u_kernel<<<BSZ / 256, 256>>>();
        pass_dual<<<pgrid, 256>>>(1);      // rB += K u_txt ; cB += K^T u_img
        upd_v_kernel<<<BSZ / 256, 256>>>();
    }

    pass_dual<<<pgrid, 256>>>(0);          // final: rA = K v_img ; cA = K^T v_txt
    finalize1_kernel<<<BSZ / 256, 256>>>(labels);
    finalize2_kernel<<<1, 1024>>>(out);
}